// round 8
// baseline (speedup 1.0000x reference)
#include <cuda_runtime.h>
#include <cuda_bf16.h>
#include <cstdint>

// Problem constants (fixed by the dataset):
//   NU = NI = 100000 nodes, E = 600000 edges per etype, DIN = DOUT = 128.
#define NNODE 100000
#define F 128
#define NE_MAX 600000
#define SCAN_BLK 1024
#define NSCAN 98            // ceil(100000 / 1024)
#define NTILE64 1563        // ceil(100000 / 64)

// ---------------------------------------------------------------------------
// Static device scratch (no allocations allowed in kernel_launch).
// ---------------------------------------------------------------------------
__device__ float          g_agg[3][(size_t)NNODE * F]; // mean-aggregated raw feats
__device__ int            g_rowptr[3][NNODE + 1];      // CSR row pointers
__device__ int            g_fill[3][NNODE];            // per-dst fill cursors
__device__ int            g_col[3][NE_MAX];            // CSR column (src) indices
__device__ int            g_part[3][128];              // scan block partials
__device__ __nv_bfloat16  g_Bw[3][2][128 * 128];       // W^T bf16 hi/lo, [n][k]

// ---------------------------------------------------------------------------
// mma.sync / ldmatrix helpers (HMMA path — valid at compute_100)
// ---------------------------------------------------------------------------
__device__ __forceinline__ uint32_t smem_u32(const void* p) {
    uint32_t a;
    asm("{ .reg .u64 t; cvta.to.shared.u64 t, %1; cvt.u32.u64 %0, t; }" : "=r"(a) : "l"(p));
    return a;
}
__device__ __forceinline__ void ldsm4(uint32_t* r, uint32_t addr) {
    asm volatile("ldmatrix.sync.aligned.m8n8.x4.shared.b16 {%0,%1,%2,%3}, [%4];"
                 : "=r"(r[0]), "=r"(r[1]), "=r"(r[2]), "=r"(r[3]) : "r"(addr));
}
__device__ __forceinline__ void mma_bf16(float* d, const uint32_t* a,
                                         uint32_t b0, uint32_t b1) {
    asm volatile(
        "mma.sync.aligned.m16n8k16.row.col.f32.bf16.bf16.f32 "
        "{%0,%1,%2,%3}, {%4,%5,%6,%7}, {%8,%9}, {%0,%1,%2,%3};"
        : "+f"(d[0]), "+f"(d[1]), "+f"(d[2]), "+f"(d[3])
        : "r"(a[0]), "r"(a[1]), "r"(a[2]), "r"(a[3]), "r"(b0), "r"(b1));
}
__device__ __forceinline__ uint32_t pkbf(__nv_bfloat16 a, __nv_bfloat16 b) {
    return (uint32_t)__bfloat16_as_ushort(a) | ((uint32_t)__bfloat16_as_ushort(b) << 16);
}

// ---------------------------------------------------------------------------
// Prep: W^T -> bf16 hi/lo split in plain [n][k] layout.  B[n][k] = W[k][n].
// ---------------------------------------------------------------------------
__global__ void prep_w_kernel(const float* __restrict__ W0, const float* __restrict__ W1,
                              const float* __restrict__ W2) {
    int e = blockIdx.y;
    const float* W = (e == 0) ? W0 : (e == 1) ? W1 : W2;
    int idx = blockIdx.x * 256 + threadIdx.x;    // 0..16383
    if (idx >= 16384) return;
    int n = idx >> 7, k = idx & 127;
    float v = W[k * F + n];
    __nv_bfloat16 hi = __float2bfloat16(v);
    __nv_bfloat16 lo = __float2bfloat16(v - __bfloat162float(hi));
    g_Bw[e][0][n * F + k] = hi;
    g_Bw[e][1][n * F + k] = lo;
}

// ---------------------------------------------------------------------------
// CSR build: zero -> histogram -> 3-phase exclusive scan -> fill
// ---------------------------------------------------------------------------
__global__ void zero_kernel() {
    int i = blockIdx.x * blockDim.x + threadIdx.x;
    if (i < 3 * (NNODE + 1)) ((int*)g_rowptr)[i] = 0;
    if (i < 3 * NNODE)       ((int*)g_fill)[i]   = 0;
}

__global__ void hist_kernel(const int* __restrict__ d0, const int* __restrict__ d1,
                            const int* __restrict__ d2, int e0, int e1, int e2) {
    int e = blockIdx.y;
    const int* d = (e == 0) ? d0 : (e == 1) ? d1 : d2;
    int n = (e == 0) ? e0 : (e == 1) ? e1 : e2;
    int i = blockIdx.x * blockDim.x + threadIdx.x;
    if (i < n) atomicAdd(&g_rowptr[e][d[i]], 1);
}

__global__ void scan_blocks_kernel() {
    int e = blockIdx.y;
    int i = blockIdx.x * SCAN_BLK + threadIdx.x;
    int val = (i < NNODE) ? g_rowptr[e][i] : 0;

    int lane = threadIdx.x & 31, wid = threadIdx.x >> 5;
    int x = val;
    #pragma unroll
    for (int o = 1; o < 32; o <<= 1) {
        int y = __shfl_up_sync(0xffffffffu, x, o);
        if (lane >= o) x += y;
    }
    __shared__ int ws[32];
    if (lane == 31) ws[wid] = x;
    __syncthreads();
    if (wid == 0) {
        int v = ws[lane];
        #pragma unroll
        for (int o = 1; o < 32; o <<= 1) {
            int y = __shfl_up_sync(0xffffffffu, v, o);
            if (lane >= o) v += y;
        }
        ws[lane] = v;   // inclusive over warp sums
    }
    __syncthreads();
    int off = wid ? ws[wid - 1] : 0;
    int excl = x - val + off;
    if (i < NNODE) g_rowptr[e][i] = excl;
    if (threadIdx.x == SCAN_BLK - 1) g_part[e][blockIdx.x] = x + off;  // block total
}

__global__ void scan_parts_kernel(int n) {
    int e = blockIdx.x, t = threadIdx.x;     // 128 threads, n <= 128
    int val = (t < n) ? g_part[e][t] : 0;
    int lane = t & 31, wid = t >> 5;
    int x = val;
    #pragma unroll
    for (int o = 1; o < 32; o <<= 1) {
        int y = __shfl_up_sync(0xffffffffu, x, o);
        if (lane >= o) x += y;
    }
    __shared__ int ws[4];
    if (lane == 31) ws[wid] = x;
    __syncthreads();
    if (t == 0) {
        int s = 0;
        for (int w = 0; w < 4; w++) { int v = ws[w]; ws[w] = s; s += v; }
    }
    __syncthreads();
    int excl = x - val + ws[wid];
    if (t < n) g_part[e][t] = excl;
}

__global__ void scan_add_kernel(int e0, int e1, int e2) {
    int e = blockIdx.y;
    int i = blockIdx.x * SCAN_BLK + threadIdx.x;
    if (i < NNODE) g_rowptr[e][i] += g_part[e][blockIdx.x];
    if (blockIdx.x == 0 && threadIdx.x == 0) {
        int ne = (e == 0) ? e0 : (e == 1) ? e1 : e2;
        g_rowptr[e][NNODE] = ne;
    }
}

__global__ void fill_kernel(const int* __restrict__ s0, const int* __restrict__ d0,
                            const int* __restrict__ s1, const int* __restrict__ d1,
                            const int* __restrict__ s2, const int* __restrict__ d2,
                            int e0, int e1, int e2) {
    int e = blockIdx.y;
    const int* s = (e == 0) ? s0 : (e == 1) ? s1 : s2;
    const int* d = (e == 0) ? d0 : (e == 1) ? d1 : d2;
    int n = (e == 0) ? e0 : (e == 1) ? e1 : e2;
    int i = blockIdx.x * blockDim.x + threadIdx.x;
    if (i < n) {
        int dd = d[i];
        int p = g_rowptr[e][dd] + atomicAdd(&g_fill[e][dd], 1);
        g_col[e][p] = s[i];
    }
}

// ---------------------------------------------------------------------------
// Mean-aggregate RAW features per dst (agg-then-project: mean_agg is linear).
// Gather source = feat tables (102MB total, L2-friendly; feat_user serves 2
// etypes). One warp per (etype, dst); lane owns one float4 of the 128-dim row.
// Rows with deg==0 are written as exact 0 (matches DGL mean semantics).
// ---------------------------------------------------------------------------
__device__ __forceinline__ float4 gather_mean(const float4* __restrict__ src,
                                              const int* __restrict__ col,
                                              int beg, int end, int lane) {
    float4 a = make_float4(0.f, 0.f, 0.f, 0.f);
    float4 b = make_float4(0.f, 0.f, 0.f, 0.f);
    int j = beg;
    for (; j + 1 < end; j += 2) {
        int c0 = col[j], c1 = col[j + 1];
        float4 v0 = src[(size_t)c0 * 32 + lane];
        float4 v1 = src[(size_t)c1 * 32 + lane];
        a.x += v0.x; a.y += v0.y; a.z += v0.z; a.w += v0.w;
        b.x += v1.x; b.y += v1.y; b.z += v1.z; b.w += v1.w;
    }
    if (j < end) {
        float4 v = src[(size_t)col[j] * 32 + lane];
        a.x += v.x; a.y += v.y; a.z += v.z; a.w += v.w;
    }
    float inv = (end > beg) ? 1.0f / (float)(end - beg) : 0.0f;
    a.x = (a.x + b.x) * inv; a.y = (a.y + b.y) * inv;
    a.z = (a.z + b.z) * inv; a.w = (a.w + b.w) * inv;
    return a;
}

__global__ void pull_agg_kernel(const float* __restrict__ feat_user,
                                const float* __restrict__ feat_item) {
    int gw   = (blockIdx.x * blockDim.x + threadIdx.x) >> 5;   // 0 .. 3*NNODE-1
    int lane = threadIdx.x & 31;
    if (gw >= 3 * NNODE) return;
    int e = gw / NNODE;
    int w = gw - e * NNODE;
    // src table per etype: ui gathers users, iu gathers items, uu gathers users
    const float4* src = (e == 1) ? (const float4*)feat_item : (const float4*)feat_user;
    int beg = g_rowptr[e][w], end = g_rowptr[e][w + 1];
    float4 m = gather_mean(src, g_col[e], beg, end, lane);
    ((float4*)g_agg[e])[(size_t)w * 32 + lane] = m;
}

// ---------------------------------------------------------------------------
// Tensor-core GEMM, writes FINAL output directly.
// BM=64, BN=128, K=128 single-shot; 8 warps (2x4); 2 CTAs/SM (~102KB smem).
// grp 0 (blockIdx.y==0): out_item = agg0 @ W0 + m0*b0      -> out[NNODE..)
// grp 1 (blockIdx.y==1): out_user = agg1@W1 + agg2@W2      (one accumulator,
//                        valid since deg==0 agg rows are 0) + m1*b1 + m2*b2
// ---------------------------------------------------------------------------
#define AS_B   272                  // smem row stride in BYTES (136 bf16)
#define SM_A_HI 0
#define SM_A_LO 17408               // 64 * 272
#define SM_B_HI 34816
#define SM_B_LO 69632               // SM_B_HI + 128*272
#define SM_TOTAL 104448             // SM_B_LO + 128*272

__global__ void __launch_bounds__(256, 2) gemm_mma_kernel(
    float* __restrict__ out,
    const float* __restrict__ b0, const float* __restrict__ b1,
    const float* __restrict__ b2) {
    extern __shared__ char smem[];
    const uint32_t sbase = smem_u32(smem);
    const int tid  = threadIdx.x;
    const int wid  = tid >> 5;
    const int lane = tid & 31;
    const int bm   = blockIdx.x * 64;
    const int grp  = blockIdx.y;          // 0 = item out, 1 = user out
    const int M    = NNODE;

    const int npass = (grp == 0) ? 1 : 2;
    int elist[2];
    const float* blist[2];
    if (grp == 0) { elist[0] = 0; blist[0] = b0; elist[1] = 0; blist[1] = b0; }
    else          { elist[0] = 1; blist[0] = b1; elist[1] = 2; blist[1] = b2; }

    // ---- per-warp ldmatrix base addresses ----
    const int wm = wid >> 2;           // 0..1  (32 rows each)
    const int wn = wid & 3;            // 0..3  (32 cols each)
    const int lrow  = lane & 15;
    const int lkoff = (lane >> 4) * 8; // bf16 units

    const uint32_t a_base0 = sbase + (uint32_t)((wm * 32 + lrow) * AS_B + lkoff * 2);
    const uint32_t b_rowk  = (uint32_t)((wn * 32 + lrow) * AS_B + lkoff * 2);
    const uint32_t bh_base = sbase + SM_B_HI + b_rowk;
    const uint32_t bl_base = sbase + SM_B_LO + b_rowk;

    float acc[2][4][4];
    #pragma unroll
    for (int t = 0; t < 2; t++)
        #pragma unroll
        for (int n = 0; n < 4; n++)
            #pragma unroll
            for (int q = 0; q < 4; q++) acc[t][n][q] = 0.f;

    for (int p = 0; p < npass; p++) {
        if (p > 0) __syncthreads();   // previous pass fully consumed smem

        const float* A = g_agg[elist[p]];
        // ---- A tile: f32 loads, bf16 hi/lo split into padded smem ----
        #pragma unroll
        for (int it = 0; it < 8; it++) {
            int idx = it * 256 + tid;                     // 0..2047
            int r = idx >> 5, c4 = idx & 31;              // row, float4-col
            float4 v = make_float4(0.f, 0.f, 0.f, 0.f);
            if (bm + r < M)
                v = *(const float4*)(A + (size_t)(bm + r) * F + c4 * 4);
            __nv_bfloat16 h0 = __float2bfloat16(v.x), h1 = __float2bfloat16(v.y);
            __nv_bfloat16 h2 = __float2bfloat16(v.z), h3 = __float2bfloat16(v.w);
            __nv_bfloat16 l0 = __float2bfloat16(v.x - __bfloat162float(h0));
            __nv_bfloat16 l1 = __float2bfloat16(v.y - __bfloat162float(h1));
            __nv_bfloat16 l2 = __float2bfloat16(v.z - __bfloat162float(h2));
            __nv_bfloat16 l3 = __float2bfloat16(v.w - __bfloat162float(h3));
            uint32_t boff = r * AS_B + c4 * 8;
            *(uint2*)(smem + SM_A_HI + boff) = make_uint2(pkbf(h0, h1), pkbf(h2, h3));
            *(uint2*)(smem + SM_A_LO + boff) = make_uint2(pkbf(l0, l1), pkbf(l2, l3));
        }
        // ---- B tile (single slot): linear 16B copies of pre-split W^T ----
        {
            const uint4* srcH = (const uint4*)g_Bw[elist[p]][0];
            const uint4* srcL = (const uint4*)g_Bw[elist[p]][1];
            #pragma unroll
            for (int it = 0; it < 8; it++) {
                int idx = it * 256 + tid;             // 0..2047
                int row = idx >> 4, c = idx & 15;
                *(uint4*)(smem + SM_B_HI + row * AS_B + c * 16) = srcH[idx];
                *(uint4*)(smem + SM_B_LO + row * AS_B + c * 16) = srcL[idx];
            }
        }
        __syncthreads();

        #pragma unroll 2
        for (int ks = 0; ks < 8; ks++) {
            const uint32_t kb = ks * 32;   // 16 bf16 = 32 bytes
            uint32_t ah[2][4], al[2][4], bh[2][4], bl[2][4];
            #pragma unroll
            for (int t = 0; t < 2; t++) {
                ldsm4(ah[t], a_base0 + SM_A_HI + t * (16 * AS_B) + kb);
                ldsm4(al[t], a_base0 + SM_A_LO + t * (16 * AS_B) + kb);
            }
            #pragma unroll
            for (int c = 0; c < 2; c++) {
                ldsm4(bh[c], bh_base + c * (16 * AS_B) + kb);
                ldsm4(bl[c], bl_base + c * (16 * AS_B) + kb);
            }
            #pragma unroll
            for (int t = 0; t < 2; t++)
                #pragma unroll
                for (int n = 0; n < 4; n++) {
                    const int c = n >> 1, s = n & 1;
                    mma_bf16(acc[t][n], ah[t], bh[c][0 + s], bh[c][2 + s]);
                    mma_bf16(acc[t][n], ah[t], bl[c][0 + s], bl[c][2 + s]);
                    mma_bf16(acc[t][n], al[t], bh[c][0 + s], bh[c][2 + s]);
                }
        }
    }

    // ---- epilogue: deg-masked bias add, write final output ----
    float* Cout = (grp == 0) ? (out + (size_t)NNODE * F) : out;
    const int* rpa = g_rowptr[elist[0]];
    const int* rpb = g_rowptr[elist[npass - 1]];

    float bva[4][2], bvb[4][2];
    #pragma unroll
    for (int n = 0; n < 4; n++) {
        const int col = wn * 32 + n * 8 + (lane & 3) * 2;
        bva[n][0] = __ldg(blist[0] + col);
        bva[n][1] = __ldg(blist[0] + col + 1);
        bvb[n][0] = (npass == 2) ? __ldg(blist[1] + col)     : 0.f;
        bvb[n][1] = (npass == 2) ? __ldg(blist[1] + col + 1) : 0.f;
    }

    #pragma unroll
    for (int t = 0; t < 2; t++) {
        const int r0 = bm + wm * 32 + t * 16 + (lane >> 2);
        #pragma unroll
        for (int half = 0; half < 2; half++) {
            const int r = r0 + half * 8;
            if (r >= M) continue;
            const float ma = (__ldg(rpa + r + 1) > __ldg(rpa + r)) ? 1.f : 0.f;
            const float mb = (npass == 2 && __ldg(rpb + r + 1) > __ldg(rpb + r)) ? 1.f : 0.f;
            #pragma unroll
            for (int n = 0; n < 4; n++) {
                const int col = wn * 32 + n * 8 + (lane & 3) * 2;
                const int q = half * 2;
                float o0 = acc[t][n][q + 0] + ma * bva[n][0] + mb * bvb[n][0];
                float o1 = acc[t][n][q + 1] + ma * bva[n][1] + mb * bvb[n][1];
                *(float2*)(Cout + (size_t)r * F + col) = make_float2(o0, o1);
            }
        }
    }
}

// ---------------------------------------------------------------------------
// kernel_launch
// ---------------------------------------------------------------------------
extern "C" void kernel_launch(void* const* d_in, const int* in_sizes, int n_in,
                              void* d_out, int out_size) {
    const float* feat_user = (const float*)d_in[0];
    const float* feat_item = (const float*)d_in[1];
    const float* W_ui = (const float*)d_in[2];
    const float* b_ui = (const float*)d_in[3];
    const float* W_iu = (const float*)d_in[4];
    const float* b_iu = (const float*)d_in[5];
    const float* W_uu = (const float*)d_in[6];
    const float* b_uu = (const float*)d_in[7];
    const int* src_ui = (const int*)d_in[8];
    const int* dst_ui = (const int*)d_in[9];
    const int* src_iu = (const int*)d_in[10];
    const int* dst_iu = (const int*)d_in[11];
    const int* src_uu = (const int*)d_in[12];
    const int* dst_uu = (const int*)d_in[13];
    float* out = (float*)d_out;

    int E0 = in_sizes[8], E1 = in_sizes[10], E2 = in_sizes[12];
    int Emax = E0 > E1 ? (E0 > E2 ? E0 : E2) : (E1 > E2 ? E1 : E2);
    int eblocks = (Emax + 255) / 256;

    // Idempotent, called every time (no static guards — harness rule).
    cudaFuncSetAttribute(gemm_mma_kernel,
                         cudaFuncAttributeMaxDynamicSharedMemorySize, SM_TOTAL);

    // CSR build
    zero_kernel<<<(3 * (NNODE + 1) + 255) / 256, 256>>>();
    hist_kernel<<<dim3(eblocks, 3), 256>>>(dst_ui, dst_iu, dst_uu, E0, E1, E2);
    prep_w_kernel<<<dim3(64, 3), 256>>>(W_ui, W_iu, W_uu);
    scan_blocks_kernel<<<dim3(NSCAN, 3), SCAN_BLK>>>();
    scan_parts_kernel<<<3, 128>>>(NSCAN);
    scan_add_kernel<<<dim3(NSCAN, 3), SCAN_BLK>>>(E0, E1, E2);
    fill_kernel<<<dim3(eblocks, 3), 256>>>(src_ui, dst_ui, src_iu, dst_iu,
                                           src_uu, dst_uu, E0, E1, E2);

    // Mean-aggregate raw features (gathers from L2-friendly feat tables)
    int ablocks = (3 * NNODE * 32 + 255) / 256;
    pull_agg_kernel<<<ablocks, 256>>>(feat_user, feat_item);

    // Project + masked bias, writing the final output directly
    gemm_mma_kernel<<<dim3(NTILE64, 2), 256, SM_TOTAL>>>(out, b_ui, b_iu, b_uu);
}